// round 13
// baseline (speedup 1.0000x reference)
#include <cuda_runtime.h>
#include <cuda_fp16.h>
#include <math.h>

#define N_NODES 10000
#define N_EDGES 160000
#define HIDDEN 128
#define NUM_RBF 32
#define N_GRAPHS 128
#define LATENT 64
#define ET 64
#define PADH 136   // half stride for 128-wide rows (272B: conflict-free for LDSM/trans)

// ---------------- scratch ----------------
__device__ float g_x[N_NODES * HIDDEN];
__device__ float g_vec[N_NODES * 3 * HIDDEN];
__device__ float g_vmix[N_NODES * 3 * HIDDEN];
__device__ float g_dx[N_NODES * HIDDEN];
__device__ float g_a[N_NODES * HIDDEN];
__device__ float g_dirn[N_EDGES * 3];
__device__ __half g_rbf[N_EDGES * NUM_RBF];
__device__ unsigned g_wrbfp[2 * 128 * 16];
__device__ float g_pooled[N_GRAPHS * 65];

// ---------------- helpers ----------------
__device__ __forceinline__ void mma_f16(float c[4], unsigned a0, unsigned a1,
                                        unsigned a2, unsigned a3,
                                        unsigned b0, unsigned b1) {
    asm volatile(
        "mma.sync.aligned.m16n8k16.row.col.f32.f16.f16.f32 "
        "{%0,%1,%2,%3}, {%4,%5,%6,%7}, {%8,%9}, {%0,%1,%2,%3};"
        : "+f"(c[0]), "+f"(c[1]), "+f"(c[2]), "+f"(c[3])
        : "r"(a0), "r"(a1), "r"(a2), "r"(a3), "r"(b0), "r"(b1));
}

__device__ __forceinline__ void ldsm_x4(unsigned& r0, unsigned& r1,
                                        unsigned& r2, unsigned& r3, unsigned addr) {
    asm volatile("ldmatrix.sync.aligned.m8n8.x4.shared.b16 {%0,%1,%2,%3}, [%4];"
                 : "=r"(r0), "=r"(r1), "=r"(r2), "=r"(r3) : "r"(addr));
}

__device__ __forceinline__ void ldsm_x4_t(unsigned& r0, unsigned& r1,
                                          unsigned& r2, unsigned& r3, unsigned addr) {
    asm volatile("ldmatrix.sync.aligned.m8n8.x4.trans.shared.b16 {%0,%1,%2,%3}, [%4];"
                 : "=r"(r0), "=r"(r1), "=r"(r2), "=r"(r3) : "r"(addr));
}

__device__ __forceinline__ void red4(float* p, float a, float b, float c, float d) {
    unsigned long long addr = (unsigned long long)p;
    asm volatile("red.global.add.v4.f32 [%0], {%1,%2,%3,%4};"
                 :: "l"(addr), "f"(a), "f"(b), "f"(c), "f"(d) : "memory");
}

__device__ __forceinline__ float silu(float v) {
    return __fdividef(v, 1.0f + __expf(-v));
}

#define H2U(p) (*(const unsigned*)(p))

// ---------------- setup ----------------
__global__ void k_setup(const int* __restrict__ z, const float* __restrict__ emb,
                        const float* __restrict__ W_rbf) {
    int i = blockIdx.x * blockDim.x + threadIdx.x;
    if (i < N_NODES * 384) g_vec[i] = 0.0f;
    if (i < N_NODES * 128) {
        g_dx[i] = 0.0f;
        int n = i >> 7, j = i & 127;
        g_x[i] = emb[z[n] * HIDDEN + j];
    }
    if (i < N_GRAPHS * 65) g_pooled[i] = 0.0f;
    if (i < 2 * 128 * 16) {
        int l = i >> 11, n = (i >> 4) & 127, kk = i & 15;
        const float* base = W_rbf + l * 32 * 128;
        __half lo = __float2half(base[(2 * kk) * 128 + n]);
        __half hi = __float2half(base[(2 * kk + 1) * 128 + n]);
        __half2 h2 = __halves2half2(lo, hi);
        g_wrbfp[i] = *(unsigned*)&h2;
    }
}

__global__ void k_geom(const float* __restrict__ pos, const int* __restrict__ ei) {
    int e = blockIdx.x * blockDim.x + threadIdx.x;
    if (e >= N_EDGES) return;
    int s = ei[e], d = ei[N_EDGES + e];
    float dx = pos[d * 3 + 0] - pos[s * 3 + 0];
    float dy = pos[d * 3 + 1] - pos[s * 3 + 1];
    float dz = pos[d * 3 + 2] - pos[s * 3 + 2];
    float r = sqrtf(dx * dx + dy * dy + dz * dz + 1e-8f);
    float inv = 1.0f / r;
    g_dirn[e * 3 + 0] = dx * inv;
    g_dirn[e * 3 + 1] = dy * inv;
    g_dirn[e * 3 + 2] = dz * inv;

    uint4* rp = (uint4*)&g_rbf[e * 32];
    uint4 z4 = make_uint4(0, 0, 0, 0);
    rp[0] = z4; rp[1] = z4; rp[2] = z4; rp[3] = z4;

    if (r < 5.0f) {
        const float c0 = 0.006737946999085467f;
        const float step = (1.0f - c0) / 31.0f;
        const float tmp = (2.0f / 32.0f) * (1.0f - c0);
        const float beta = 1.0f / (tmp * tmp);
        float cut = 0.5f * (__cosf(0.6283185307179586f * r) + 1.0f);
        float er = __expf(-r);
        int kc = (int)((er - c0) * (1.0f / step));
        int base = kc - 8;
        base = base < 0 ? 0 : (base > 15 ? 15 : base);
#pragma unroll
        for (int kk = 0; kk < 17; ++kk) {
            int k = base + kk;
            float m = c0 + (float)k * step;
            float dd = er - m;
            g_rbf[e * 32 + k] = __float2half(cut * __expf(-beta * dd * dd));
        }
    }
}

// ---------------- pipelined multi-tile GEMM runner ----------------
// W staged once per CTA; per tile: mma -> sync -> stage A(next) || epilogue -> sync.
// MODE 0: A row-major RxK. MODE 2 (K=256): A-row = [x | vnorm(A2)].
template <int K, int MODE>
__device__ __forceinline__ void stage_A(
    const float* __restrict__ A, const float* __restrict__ A2,
    int R, int r0, int clearA, __half* A_h) {
    constexpr int PK = K + 8;
    int tid = threadIdx.x;
    for (int m4 = tid; m4 < 64 * (K / 4); m4 += 256) {
        int r = m4 / (K / 4), c = (m4 % (K / 4)) * 4;
        int rr = r0 + r;
        float4 v = make_float4(0.f, 0.f, 0.f, 0.f);
        if (rr < R) {
            if (MODE == 2) {
                if (c < 128) {
                    v = *(const float4*)&A[rr * 128 + c];
                } else {
                    int cc = c - 128;
                    float4 a0 = *(const float4*)&A2[(rr * 3 + 0) * 128 + cc];
                    float4 a1 = *(const float4*)&A2[(rr * 3 + 1) * 128 + cc];
                    float4 a2 = *(const float4*)&A2[(rr * 3 + 2) * 128 + cc];
                    v.x = sqrtf(a0.x * a0.x + a1.x * a1.x + a2.x * a2.x + 1e-8f);
                    v.y = sqrtf(a0.y * a0.y + a1.y * a1.y + a2.y * a2.y + 1e-8f);
                    v.z = sqrtf(a0.z * a0.z + a1.z * a1.z + a2.z * a2.z + 1e-8f);
                    v.w = sqrtf(a0.w * a0.w + a1.w * a1.w + a2.w * a2.w + 1e-8f);
                }
            } else {
                v = *(const float4*)&A[rr * K + c];
                if (clearA)
                    *(float4*)&((float*)A)[rr * K + c] = make_float4(0.f, 0.f, 0.f, 0.f);
            }
        }
        __half2 h0 = __floats2half2_rn(v.x, v.y);
        __half2 h1 = __floats2half2_rn(v.z, v.w);
        *(uint2*)&A_h[r * PK + c] = make_uint2(*(unsigned*)&h0, *(unsigned*)&h1);
    }
}

template <int K, int MODE>
__device__ __forceinline__ void gemm_run(
    const float* __restrict__ A, const float* __restrict__ A2,
    const float* __restrict__ W, const float* __restrict__ bias,
    float* __restrict__ C, int R, int t0, int tstep,
    int accum, int act, int clearA, __half* smh) {
    constexpr int PK = K + 8;
    __half* W_h = smh;            // [K][PADH]
    __half* A_h = W_h + K * PADH; // [64][PK]
    int tid = threadIdx.x;
    int w = tid >> 5, lane = tid & 31, gid = lane >> 2, tig = lane & 3;

    // stage W [k][n] once
    for (int m4 = tid; m4 < K * 32; m4 += 256) {
        int k = m4 >> 5, n = (m4 & 31) * 4;
        float4 v = *(const float4*)&W[k * 128 + n];
        __half2 h0 = __floats2half2_rn(v.x, v.y);
        __half2 h1 = __floats2half2_rn(v.z, v.w);
        *(uint2*)&W_h[k * PADH + n] = make_uint2(*(unsigned*)&h0, *(unsigned*)&h1);
    }

    int nT = (R + 63) >> 6;
    int t = t0;
    if (t < nT) stage_A<K, MODE>(A, A2, R, t << 6, clearA, A_h);
    __syncthreads();

    int m0 = (w & 3) * 16;
    int nbase = (w >> 2) * 64;
    int sec = lane >> 3, r8 = lane & 7;
    unsigned a_base = (unsigned)__cvta_generic_to_shared(A_h);
    unsigned w_base = (unsigned)__cvta_generic_to_shared(W_h);
    unsigned aAddr = a_base +
        (((m0 + r8 + ((sec & 1) << 3)) * PK + ((sec >> 1) << 3)) << 1);
    unsigned bAddrT = w_base +
        (((((sec & 1) << 3) + r8) * PADH + ((sec >> 1) << 3) + nbase) << 1);

    for (; t < nT; t += tstep) {
        int r0 = t << 6;

        float acc[8][4];
#pragma unroll
        for (int it = 0; it < 8; ++it)
#pragma unroll
            for (int q = 0; q < 4; ++q) acc[it][q] = 0.0f;

#pragma unroll
        for (int ks = 0; ks < K / 16; ++ks) {
            unsigned koff_a = ks * 32;
            unsigned koff_b = ks * 16 * PADH * 2;
            unsigned a0, a1, a2, a3;
            ldsm_x4(a0, a1, a2, a3, aAddr + koff_a);
#pragma unroll
            for (int j = 0; j < 4; ++j) {
                unsigned b0, b1, b2, b3;
                ldsm_x4_t(b0, b1, b2, b3, bAddrT + koff_b + j * 32);
                mma_f16(acc[2 * j], a0, a1, a2, a3, b0, b1);
                mma_f16(acc[2 * j + 1], a0, a1, a2, a3, b2, b3);
            }
        }
        __syncthreads();   // all mma reads of A_h done

        // overlap next tile's A staging with this tile's epilogue
        int tn = t + tstep;
        if (tn < nT) stage_A<K, MODE>(A, A2, R, tn << 6, clearA, A_h);

#pragma unroll
        for (int it = 0; it < 8; ++it) {
            int n0 = nbase + it * 8;
            int col = n0 + 2 * tig;
            float bb0 = bias ? bias[col] : 0.0f;
            float bb1 = bias ? bias[col + 1] : 0.0f;
#pragma unroll
            for (int h = 0; h < 2; ++h) {
                int row = r0 + m0 + gid + h * 8;
                if (row < R) {
                    float v0 = acc[it][2 * h + 0] + bb0;
                    float v1 = acc[it][2 * h + 1] + bb1;
                    if (accum) {
                        v0 += C[row * 128 + col];
                        v1 += C[row * 128 + col + 1];
                    }
                    if (act) { v0 = silu(v0); v1 = silu(v1); }
                    C[row * 128 + col] = v0;
                    C[row * 128 + col + 1] = v1;
                }
            }
        }
        __syncthreads();   // A(t+1) staged and epilogue done
    }
}

// merged dual GEMM: branch1 (accum into C1, optional clearA) ∥ branch2
__global__ __launch_bounds__(256, 3) void k_gemm2(
    const float* A1, const float* W1, float* C1, int R1, int clear1,
    const float* A2, const float* W2, float* C2, int R2, int nC1) {
    extern __shared__ __half smh[];
    if ((int)blockIdx.x < nC1)
        gemm_run<128, 0>(A1, nullptr, W1, nullptr, C1, R1,
                         blockIdx.x, nC1, 1, 0, clear1, smh);
    else
        gemm_run<128, 0>(A2, nullptr, W2, nullptr, C2, R2,
                         (int)blockIdx.x - nC1, (int)gridDim.x - nC1, 0, 0, 0, smh);
}

// a = silu([x | vnorm(v2)] @ W_a + b_a)
__global__ __launch_bounds__(256, 2) void k_gemma(
    const float* X, const float* V2, const float* W, const float* bias,
    float* C, int R) {
    extern __shared__ __half smh[];
    gemm_run<256, 2>(X, V2, W, bias, C, R, blockIdx.x, gridDim.x, 0, 1, 0, smh);
}

// ---------------- fused fp16 edge kernel ----------------
__global__ __launch_bounds__(512, 3) void k_edge(
    const int* __restrict__ ei, const unsigned* __restrict__ wrbfp,
    const float* __restrict__ W1, int novmix) {
    extern __shared__ __half smh[];
    __half* W1KN   = smh;                      // [128 k][PADH n]
    __half* filt_h = W1KN + 128 * PADH;        // [64 e][PADH c]
    __half* t_h    = filt_h + ET * PADH;       // [64 e][PADH k] (phi alias)
    float* dirn_s = (float*)(t_h + ET * PADH);
    int* src_s = (int*)(dirn_s + 192);
    int* dst_s = src_s + ET;

    int tid = threadIdx.x;
    int w = tid >> 5, lane = tid & 31, gid = lane >> 2, tig = lane & 3;

    for (int m4 = tid; m4 < 128 * 32; m4 += 512) {
        int k = m4 >> 5, n = (m4 & 31) * 4;
        float4 v = *(const float4*)&W1[k * 128 + n];
        __half2 h0 = __floats2half2_rn(v.x, v.y);
        __half2 h1 = __floats2half2_rn(v.z, v.w);
        *(uint2*)&W1KN[k * PADH + n] = make_uint2(*(unsigned*)&h0, *(unsigned*)&h1);
    }

    int m0 = (w & 3) * 16;
    int nbase = (w >> 2) * 32;
    int c4 = lane * 4;

    int sec = lane >> 3, r8 = lane & 7;
    unsigned t_base  = (unsigned)__cvta_generic_to_shared(t_h);
    unsigned w1_base = (unsigned)__cvta_generic_to_shared(W1KN);
    unsigned aAddr = t_base +
        (((m0 + r8 + ((sec & 1) << 3)) * PADH + ((sec >> 1) << 3)) << 1);
    unsigned bAddrT = w1_base +
        (((((sec & 1) << 3) + r8) * PADH + ((sec >> 1) << 3) + nbase) << 1);

    int nTiles = N_EDGES / ET;
    for (int t = blockIdx.x; t < nTiles; t += gridDim.x) {
        int e0 = t * ET;
        __syncthreads();

        if (tid < ET) src_s[tid] = ei[e0 + tid];
        else if (tid < 2 * ET) dst_s[tid - ET] = ei[N_EDGES + e0 + (tid - ET)];
        if (tid < ET * 3) dirn_s[tid] = g_dirn[e0 * 3 + tid];
        __syncthreads();

        // filt = rbf @ Wrbf
        {
            float acc[4][4];
#pragma unroll
            for (int it = 0; it < 4; ++it)
#pragma unroll
                for (int q = 0; q < 4; ++q) acc[it][q] = 0.0f;
#pragma unroll
            for (int ks = 0; ks < 2; ++ks) {
                int k0 = ks * 16;
                unsigned a0 = H2U(&g_rbf[(e0 + m0 + gid) * 32 + k0 + 2 * tig]);
                unsigned a1 = H2U(&g_rbf[(e0 + m0 + gid + 8) * 32 + k0 + 2 * tig]);
                unsigned a2 = H2U(&g_rbf[(e0 + m0 + gid) * 32 + k0 + 2 * tig + 8]);
                unsigned a3 = H2U(&g_rbf[(e0 + m0 + gid + 8) * 32 + k0 + 2 * tig + 8]);
#pragma unroll
                for (int it = 0; it < 4; ++it) {
                    int n0 = nbase + it * 8;
                    unsigned b0 = wrbfp[(n0 + gid) * 16 + 8 * ks + tig];
                    unsigned b1 = wrbfp[(n0 + gid) * 16 + 8 * ks + tig + 4];
                    mma_f16(acc[it], a0, a1, a2, a3, b0, b1);
                }
            }
#pragma unroll
            for (int it = 0; it < 4; ++it) {
                int n0 = nbase + it * 8;
                *(__half2*)&filt_h[(m0 + gid) * PADH + n0 + 2 * tig] =
                    __floats2half2_rn(acc[it][0], acc[it][1]);
                *(__half2*)&filt_h[(m0 + gid + 8) * PADH + n0 + 2 * tig] =
                    __floats2half2_rn(acc[it][2], acc[it][3]);
            }
        }
        __syncthreads();

        // t[e][c] = x[src[e]][c] * filt[e][c]
#pragma unroll
        for (int q = 0; q < 4; ++q) {
            int e = w + 16 * q;
            int s = src_s[e];
            float4 xv = *(const float4*)&g_x[s * 128 + c4];
            uint2 fu = *(const uint2*)&filt_h[e * PADH + c4];
            float2 f01 = __half22float2(*(__half2*)&fu.x);
            float2 f23 = __half22float2(*(__half2*)&fu.y);
            __half2 h0 = __floats2half2_rn(xv.x * f01.x, xv.y * f01.y);
            __half2 h1 = __floats2half2_rn(xv.z * f23.x, xv.w * f23.y);
            *(uint2*)&t_h[e * PADH + c4] = make_uint2(*(unsigned*)&h0, *(unsigned*)&h1);
        }
        __syncthreads();

        // phi = t @ W1
        float acc[4][4];
#pragma unroll
        for (int it = 0; it < 4; ++it)
#pragma unroll
            for (int q = 0; q < 4; ++q) acc[it][q] = 0.0f;
#pragma unroll
        for (int ks = 0; ks < 8; ++ks) {
            unsigned koff_a = ks * 32;
            unsigned koff_b = ks * 16 * PADH * 2;
            unsigned a0, a1, a2, a3;
            ldsm_x4(a0, a1, a2, a3, aAddr + koff_a);
            unsigned b00, b01, b10, b11;
            ldsm_x4_t(b00, b01, b10, b11, bAddrT + koff_b);
            unsigned b20, b21, b30, b31;
            ldsm_x4_t(b20, b21, b30, b31, bAddrT + koff_b + 32);
            mma_f16(acc[0], a0, a1, a2, a3, b00, b01);
            mma_f16(acc[1], a0, a1, a2, a3, b10, b11);
            mma_f16(acc[2], a0, a1, a2, a3, b20, b21);
            mma_f16(acc[3], a0, a1, a2, a3, b30, b31);
        }
        __syncthreads();

#pragma unroll
        for (int it = 0; it < 4; ++it) {
            int n0 = nbase + it * 8;
            *(__half2*)&t_h[(m0 + gid) * PADH + n0 + 2 * tig] =
                __floats2half2_rn(silu(acc[it][0]), silu(acc[it][1]));
            *(__half2*)&t_h[(m0 + gid + 8) * PADH + n0 + 2 * tig] =
                __floats2half2_rn(silu(acc[it][2]), silu(acc[it][3]));
        }
        __syncthreads();

        // scatter
#pragma unroll
        for (int q = 0; q < 4; ++q) {
            int e = w + 16 * q;
            int s = src_s[e], d = dst_s[e];
            uint2 pu = *(const uint2*)&t_h[e * PADH + c4];
            float2 p01 = __half22float2(*(__half2*)&pu.x);
            float2 p23 = __half22float2(*(__half2*)&pu.y);
            float d0 = dirn_s[e * 3 + 0];
            float d1 = dirn_s[e * 3 + 1];
            float d2 = dirn_s[e * 3 + 2];
            red4(&g_dx[d * 128 + c4], p01.x, p01.y, p23.x, p23.y);
            if (novmix) {
                red4(&g_vec[(d * 3 + 0) * 128 + c4],
                     p01.x * d0, p01.y * d0, p23.x * d0, p23.y * d0);
                red4(&g_vec[(d * 3 + 1) * 128 + c4],
                     p01.x * d1, p01.y * d1, p23.x * d1, p23.y * d1);
                red4(&g_vec[(d * 3 + 2) * 128 + c4],
                     p01.x * d2, p01.y * d2, p23.x * d2, p23.y * d2);
            } else {
                uint2 fu = *(const uint2*)&filt_h[e * PADH + c4];
                float2 f01 = __half22float2(*(__half2*)&fu.x);
                float2 f23 = __half22float2(*(__half2*)&fu.y);
                float4 m0v = *(const float4*)&g_vmix[(s * 3 + 0) * 128 + c4];
                red4(&g_vec[(d * 3 + 0) * 128 + c4],
                     m0v.x * f01.x + p01.x * d0, m0v.y * f01.y + p01.y * d0,
                     m0v.z * f23.x + p23.x * d0, m0v.w * f23.y + p23.y * d0);
                float4 m1v = *(const float4*)&g_vmix[(s * 3 + 1) * 128 + c4];
                red4(&g_vec[(d * 3 + 1) * 128 + c4],
                     m1v.x * f01.x + p01.x * d1, m1v.y * f01.y + p01.y * d1,
                     m1v.z * f23.x + p23.x * d1, m1v.w * f23.y + p23.y * d1);
                float4 m2v = *(const float4*)&g_vmix[(s * 3 + 2) * 128 + c4];
                red4(&g_vec[(d * 3 + 2) * 128 + c4],
                     m2v.x * f01.x + p01.x * d2, m2v.y * f01.y + p01.y * d2,
                     m2v.z * f23.x + p23.x * d2, m2v.w * f23.y + p23.y * d2);
            }
        }
    }
}

__global__ void k_pool(const float* __restrict__ a, const int* __restrict__ batch,
                       const float* __restrict__ Wb, const float* __restrict__ bb) {
    __shared__ float Wb_s[128 * 65];
    __shared__ float bb_s[65];
    __shared__ float a_s[4][128];
    int tx = threadIdx.x, ty = threadIdx.y;
    int tid = ty * 65 + tx;
    for (int m = tid; m < 128 * 65; m += 260) Wb_s[m] = Wb[m];
    if (tid < 65) bb_s[tid] = bb[tid];
    __syncthreads();
    for (int base = blockIdx.x * 4; base < N_NODES; base += gridDim.x * 4) {
        int n = base + ty;
        a_s[ty][tx] = a[n * 128 + tx];
        if (tx + 65 < 128) a_s[ty][tx + 65] = a[n * 128 + tx + 65];
        __syncthreads();
        float acc = bb_s[tx];
#pragma unroll 4
        for (int jj = 0; jj < 128; ++jj) acc += a_s[ty][jj] * Wb_s[jj * 65 + tx];
        atomicAdd(&g_pooled[batch[n] * 65 + tx], acc);
        __syncthreads();
    }
}

__global__ void k_final(float* __restrict__ out) {
    int idx = blockIdx.x * blockDim.x + threadIdx.x;
    if (idx < N_GRAPHS * LATENT) {
        int g = idx / LATENT, k = idx % LATENT;
        out[idx] = g_pooled[g * 65 + k];
    } else if (idx < N_GRAPHS * LATENT + N_GRAPHS) {
        int g = idx - N_GRAPHS * LATENT;
        float lv = g_pooled[g * 65 + 64];
        out[idx] = fminf(fmaxf(lv, -10.0f), 2.0f);
    }
}

extern "C" void kernel_launch(void* const* d_in, const int* in_sizes, int n_in,
                              void* d_out, int out_size) {
    (void)in_sizes; (void)n_in; (void)out_size;
    const int* z = (const int*)d_in[0];
    const float* pos = (const float*)d_in[1];
    const int* batch = (const int*)d_in[2];
    const int* ei = (const int*)d_in[3];
    const float* embed = (const float*)d_in[4];
    const float* W_rbf = (const float*)d_in[5];
    const float* W1 = (const float*)d_in[6];
    const float* Wo = (const float*)d_in[7];
    const float* Wv = (const float*)d_in[8];
    const float* Wvec2 = (const float*)d_in[10];
    const float* W_a = (const float*)d_in[11];
    const float* b_a = (const float*)d_in[12];
    const float* W_b = (const float*)d_in[13];
    const float* b_b = (const float*)d_in[14];
    float* out = (float*)d_out;

    float *p_x, *p_vec, *p_vmix, *p_dx, *p_a;
    unsigned* p_wrbfp;
    cudaGetSymbolAddress((void**)&p_x, g_x);
    cudaGetSymbolAddress((void**)&p_vec, g_vec);
    cudaGetSymbolAddress((void**)&p_vmix, g_vmix);
    cudaGetSymbolAddress((void**)&p_dx, g_dx);
    cudaGetSymbolAddress((void**)&p_a, g_a);
    cudaGetSymbolAddress((void**)&p_wrbfp, g_wrbfp);

    size_t smem_g128 = (size_t)(128 * PADH + 64 * 136) * 2;       // 52224
    size_t smem_g256 = (size_t)(256 * PADH + 64 * 264) * 2;       // 103424
    size_t smem_edge = (size_t)(128 * PADH + 2 * ET * PADH) * 2
                       + 192 * 4 + 2 * ET * 4;                    // ~69.3 KB
    cudaFuncSetAttribute(k_gemm2, cudaFuncAttributeMaxDynamicSharedMemorySize, (int)smem_g128);
    cudaFuncSetAttribute(k_gemma, cudaFuncAttributeMaxDynamicSharedMemorySize, (int)smem_g256);
    cudaFuncSetAttribute(k_edge, cudaFuncAttributeMaxDynamicSharedMemorySize, (int)smem_edge);

    // W staged once per CTA; ~2 tiles per CTA via strided tile assignment
    int nC1 = 79;    // small branch: 157 tiles
    int nC2 = 235;   // big branch:   469 tiles
    int nCa = 79;    // Wa: 157 tiles

    k_setup<<<(N_NODES * 384 + 255) / 256, 256>>>(z, embed, W_rbf);
    k_geom<<<(N_EDGES + 255) / 256, 256>>>(pos, ei);

    // ---- layer 0 (vmix == 0) ----
    k_edge<<<444, 512, smem_edge>>>(ei, p_wrbfp, W1, 1);
    // merged: x += dx@Wo0 (clear dx) ∥ vmix = vec@Wv1
    k_gemm2<<<nC1 + nC2, 256, smem_g128>>>(
        p_dx, Wo, p_x, N_NODES, 1,
        p_vec, Wv + 128 * 128, p_vmix, N_NODES * 3, nC1);

    // ---- layer 1 ----
    k_edge<<<444, 512, smem_edge>>>(ei, p_wrbfp + 128 * 16, W1 + 128 * 128, 0);
    // merged: x += dx@Wo1 ∥ v2 = vec@Wvec2
    k_gemm2<<<nC1 + nC2, 256, smem_g128>>>(
        p_dx, Wo + 128 * 128, p_x, N_NODES, 0,
        p_vec, Wvec2, p_vmix, N_NODES * 3, nC1);

    // a = silu([x | vnorm(v2)] @ W_a + b_a)
    k_gemma<<<nCa, 256, smem_g256>>>(p_x, p_vmix, W_a, b_a, p_a, N_NODES);

    dim3 pb(65, 4);
    k_pool<<<296, pb>>>(p_a, batch, W_b, b_b);

    k_final<<<(N_GRAPHS * LATENT + N_GRAPHS + 255) / 256, 256>>>(out);
}

// round 15
// speedup vs baseline: 1.0531x; 1.0531x over previous
#include <cuda_runtime.h>
#include <cuda_fp16.h>
#include <math.h>

#define N_NODES 10000
#define N_EDGES 160000
#define HIDDEN 128
#define NUM_RBF 32
#define N_GRAPHS 128
#define LATENT 64
#define ET 64
#define PADH 136   // half stride for 128-wide rows (272B: conflict-free for LDSM/trans)

// ---------------- scratch ----------------
__device__ float g_x[N_NODES * HIDDEN];
__device__ float g_vec[N_NODES * 3 * HIDDEN];
__device__ float g_vmix[N_NODES * 3 * HIDDEN];
__device__ float g_dx[N_NODES * HIDDEN];
__device__ float g_a[N_NODES * HIDDEN];
__device__ float g_dirn[N_EDGES * 3];
__device__ __half g_rbf[N_EDGES * NUM_RBF];
__device__ unsigned g_wrbfp[2 * 128 * 16];
__device__ float g_pooled[N_GRAPHS * 65];

// ---------------- helpers ----------------
__device__ __forceinline__ void mma_f16(float c[4], unsigned a0, unsigned a1,
                                        unsigned a2, unsigned a3,
                                        unsigned b0, unsigned b1) {
    asm volatile(
        "mma.sync.aligned.m16n8k16.row.col.f32.f16.f16.f32 "
        "{%0,%1,%2,%3}, {%4,%5,%6,%7}, {%8,%9}, {%0,%1,%2,%3};"
        : "+f"(c[0]), "+f"(c[1]), "+f"(c[2]), "+f"(c[3])
        : "r"(a0), "r"(a1), "r"(a2), "r"(a3), "r"(b0), "r"(b1));
}

__device__ __forceinline__ void ldsm_x4(unsigned& r0, unsigned& r1,
                                        unsigned& r2, unsigned& r3, unsigned addr) {
    asm volatile("ldmatrix.sync.aligned.m8n8.x4.shared.b16 {%0,%1,%2,%3}, [%4];"
                 : "=r"(r0), "=r"(r1), "=r"(r2), "=r"(r3) : "r"(addr));
}

__device__ __forceinline__ void ldsm_x4_t(unsigned& r0, unsigned& r1,
                                          unsigned& r2, unsigned& r3, unsigned addr) {
    asm volatile("ldmatrix.sync.aligned.m8n8.x4.trans.shared.b16 {%0,%1,%2,%3}, [%4];"
                 : "=r"(r0), "=r"(r1), "=r"(r2), "=r"(r3) : "r"(addr));
}

__device__ __forceinline__ void red4(float* p, float a, float b, float c, float d) {
    unsigned long long addr = (unsigned long long)p;
    asm volatile("red.global.add.v4.f32 [%0], {%1,%2,%3,%4};"
                 :: "l"(addr), "f"(a), "f"(b), "f"(c), "f"(d) : "memory");
}

__device__ __forceinline__ void red2(float* p, float a, float b) {
    unsigned long long addr = (unsigned long long)p;
    asm volatile("red.global.add.v2.f32 [%0], {%1,%2};"
                 :: "l"(addr), "f"(a), "f"(b) : "memory");
}

__device__ __forceinline__ float silu(float v) {
    return __fdividef(v, 1.0f + __expf(-v));
}

#define H2U(p) (*(const unsigned*)(p))

// ---------------- setup ----------------
__global__ void k_setup(const int* __restrict__ z, const float* __restrict__ emb,
                        const float* __restrict__ W_rbf) {
    int i = blockIdx.x * blockDim.x + threadIdx.x;
    if (i < N_NODES * 384) g_vec[i] = 0.0f;
    if (i < N_NODES * 128) {
        g_dx[i] = 0.0f;
        int n = i >> 7, j = i & 127;
        g_x[i] = emb[z[n] * HIDDEN + j];
    }
    if (i < N_GRAPHS * 65) g_pooled[i] = 0.0f;
    if (i < 2 * 128 * 16) {
        int l = i >> 11, n = (i >> 4) & 127, kk = i & 15;
        const float* base = W_rbf + l * 32 * 128;
        __half lo = __float2half(base[(2 * kk) * 128 + n]);
        __half hi = __float2half(base[(2 * kk + 1) * 128 + n]);
        __half2 h2 = __halves2half2(lo, hi);
        g_wrbfp[i] = *(unsigned*)&h2;
    }
}

__global__ void k_geom(const float* __restrict__ pos, const int* __restrict__ ei) {
    int e = blockIdx.x * blockDim.x + threadIdx.x;
    if (e >= N_EDGES) return;
    int s = ei[e], d = ei[N_EDGES + e];
    float dx = pos[d * 3 + 0] - pos[s * 3 + 0];
    float dy = pos[d * 3 + 1] - pos[s * 3 + 1];
    float dz = pos[d * 3 + 2] - pos[s * 3 + 2];
    float r = sqrtf(dx * dx + dy * dy + dz * dz + 1e-8f);
    float inv = 1.0f / r;
    g_dirn[e * 3 + 0] = dx * inv;
    g_dirn[e * 3 + 1] = dy * inv;
    g_dirn[e * 3 + 2] = dz * inv;

    uint4* rp = (uint4*)&g_rbf[e * 32];
    uint4 z4 = make_uint4(0, 0, 0, 0);
    rp[0] = z4; rp[1] = z4; rp[2] = z4; rp[3] = z4;

    if (r < 5.0f) {
        const float c0 = 0.006737946999085467f;
        const float step = (1.0f - c0) / 31.0f;
        const float tmp = (2.0f / 32.0f) * (1.0f - c0);
        const float beta = 1.0f / (tmp * tmp);
        float cut = 0.5f * (__cosf(0.6283185307179586f * r) + 1.0f);
        float er = __expf(-r);
        int kc = (int)((er - c0) * (1.0f / step));
        int base = kc - 8;
        base = base < 0 ? 0 : (base > 15 ? 15 : base);
#pragma unroll
        for (int kk = 0; kk < 17; ++kk) {
            int k = base + kk;
            float m = c0 + (float)k * step;
            float dd = er - m;
            g_rbf[e * 32 + k] = __float2half(cut * __expf(-beta * dd * dd));
        }
    }
}

// ---------------- one 64-row GEMM tile (fp16 mma, W staged [k][n], trans-LDSM B) ----
// MODE 0: A row-major RxK.  MODE 2 (K=256): A-row = [x | vnorm(A2)].
// accum=1 -> epilogue uses red.global.add.v2 (no C read); else plain store.
template <int K, int MODE>
__device__ __forceinline__ void gemm_tile(
    const float* __restrict__ A, const float* __restrict__ A2,
    const float* __restrict__ W, const float* __restrict__ bias,
    float* __restrict__ C, int R, int r0, int accum, int act, int clearA,
    __half* smh) {
    constexpr int PK = K + 8;
    __half* W_h = smh;            // [K][PADH]  (k rows, n cols)
    __half* A_h = W_h + K * PADH; // [64][PK]
    int tid = threadIdx.x;
    int w = tid >> 5, lane = tid & 31, gid = lane >> 2, tig = lane & 3;

    // stage W [k][n]: coalesced float4 loads, vector half stores
    for (int m4 = tid; m4 < K * 32; m4 += 256) {
        int k = m4 >> 5, n = (m4 & 31) * 4;
        float4 v = *(const float4*)&W[k * 128 + n];
        __half2 h0 = __floats2half2_rn(v.x, v.y);
        __half2 h1 = __floats2half2_rn(v.z, v.w);
        *(uint2*)&W_h[k * PADH + n] = make_uint2(*(unsigned*)&h0, *(unsigned*)&h1);
    }
    // stage A
    for (int m4 = tid; m4 < 64 * (K / 4); m4 += 256) {
        int r = m4 / (K / 4), c = (m4 % (K / 4)) * 4;
        int rr = r0 + r;
        float4 v = make_float4(0.f, 0.f, 0.f, 0.f);
        if (rr < R) {
            if (MODE == 2) {
                if (c < 128) {
                    v = *(const float4*)&A[rr * 128 + c];
                } else {
                    int cc = c - 128;
                    float4 a0 = *(const float4*)&A2[(rr * 3 + 0) * 128 + cc];
                    float4 a1 = *(const float4*)&A2[(rr * 3 + 1) * 128 + cc];
                    float4 a2 = *(const float4*)&A2[(rr * 3 + 2) * 128 + cc];
                    v.x = sqrtf(a0.x * a0.x + a1.x * a1.x + a2.x * a2.x + 1e-8f);
                    v.y = sqrtf(a0.y * a0.y + a1.y * a1.y + a2.y * a2.y + 1e-8f);
                    v.z = sqrtf(a0.z * a0.z + a1.z * a1.z + a2.z * a2.z + 1e-8f);
                    v.w = sqrtf(a0.w * a0.w + a1.w * a1.w + a2.w * a2.w + 1e-8f);
                }
            } else {
                v = *(const float4*)&A[rr * K + c];
                if (clearA)
                    *(float4*)&((float*)A)[rr * K + c] = make_float4(0.f, 0.f, 0.f, 0.f);
            }
        }
        __half2 h0 = __floats2half2_rn(v.x, v.y);
        __half2 h1 = __floats2half2_rn(v.z, v.w);
        *(uint2*)&A_h[r * PK + c] = make_uint2(*(unsigned*)&h0, *(unsigned*)&h1);
    }
    __syncthreads();

    int m0 = (w & 3) * 16;
    int nbase = (w >> 2) * 64;
    int sec = lane >> 3, r8 = lane & 7;
    unsigned a_base = (unsigned)__cvta_generic_to_shared(A_h);
    unsigned w_base = (unsigned)__cvta_generic_to_shared(W_h);
    unsigned aAddr = a_base +
        (((m0 + r8 + ((sec & 1) << 3)) * PK + ((sec >> 1) << 3)) << 1);
    unsigned bAddrT = w_base +
        (((((sec & 1) << 3) + r8) * PADH + ((sec >> 1) << 3) + nbase) << 1);

    float acc[8][4];
#pragma unroll
    for (int it = 0; it < 8; ++it)
#pragma unroll
        for (int q = 0; q < 4; ++q) acc[it][q] = 0.0f;

#pragma unroll
    for (int ks = 0; ks < K / 16; ++ks) {
        unsigned koff_a = ks * 32;
        unsigned koff_b = ks * 16 * PADH * 2;
        unsigned a0, a1, a2, a3;
        ldsm_x4(a0, a1, a2, a3, aAddr + koff_a);
#pragma unroll
        for (int j = 0; j < 4; ++j) {
            unsigned b0, b1, b2, b3;
            ldsm_x4_t(b0, b1, b2, b3, bAddrT + koff_b + j * 32);
            mma_f16(acc[2 * j], a0, a1, a2, a3, b0, b1);
            mma_f16(acc[2 * j + 1], a0, a1, a2, a3, b2, b3);
        }
    }

#pragma unroll
    for (int it = 0; it < 8; ++it) {
        int n0 = nbase + it * 8;
        int col = n0 + 2 * tig;
        float bb0 = bias ? bias[col] : 0.0f;
        float bb1 = bias ? bias[col + 1] : 0.0f;
#pragma unroll
        for (int h = 0; h < 2; ++h) {
            int row = r0 + m0 + gid + h * 8;
            if (row < R) {
                float v0 = acc[it][2 * h + 0] + bb0;
                float v1 = acc[it][2 * h + 1] + bb1;
                if (act) { v0 = silu(v0); v1 = silu(v1); }
                if (accum) {
                    red2(&C[row * 128 + col], v0, v1);   // no C read
                } else {
                    C[row * 128 + col] = v0;
                    C[row * 128 + col + 1] = v1;
                }
            }
        }
    }
}

// merged dual GEMM (R12 structure: one tile per CTA)
__global__ __launch_bounds__(256, 3) void k_gemm2(
    const float* A1, const float* W1, float* C1, int R1, int clear1,
    const float* A2, const float* W2, float* C2, int R2) {
    extern __shared__ __half smh[];
    int nT1 = (R1 + 63) >> 6;
    if ((int)blockIdx.x < nT1)
        gemm_tile<128, 0>(A1, nullptr, W1, nullptr, C1, R1, blockIdx.x << 6,
                          1, 0, clear1, smh);
    else
        gemm_tile<128, 0>(A2, nullptr, W2, nullptr, C2, R2,
                          ((int)blockIdx.x - nT1) << 6, 0, 0, 0, smh);
}

// a = silu([x | vnorm(v2)] @ W_a + b_a)
__global__ __launch_bounds__(256, 2) void k_gemma(
    const float* X, const float* V2, const float* W, const float* bias,
    float* C, int R) {
    extern __shared__ __half smh[];
    gemm_tile<256, 2>(X, V2, W, bias, C, R, blockIdx.x << 6, 0, 1, 0, smh);
}

// ---------------- fused fp16 edge kernel ----------------
__global__ __launch_bounds__(512, 3) void k_edge(
    const int* __restrict__ ei, const unsigned* __restrict__ wrbfp,
    const float* __restrict__ W1, int novmix) {
    extern __shared__ __half smh[];
    __half* W1KN   = smh;                      // [128 k][PADH n]
    __half* filt_h = W1KN + 128 * PADH;        // [64 e][PADH c]
    __half* t_h    = filt_h + ET * PADH;       // [64 e][PADH k] (phi alias)
    float* dirn_s = (float*)(t_h + ET * PADH);
    int* src_s = (int*)(dirn_s + 192);
    int* dst_s = src_s + ET;

    int tid = threadIdx.x;
    int w = tid >> 5, lane = tid & 31, gid = lane >> 2, tig = lane & 3;

    for (int m4 = tid; m4 < 128 * 32; m4 += 512) {
        int k = m4 >> 5, n = (m4 & 31) * 4;
        float4 v = *(const float4*)&W1[k * 128 + n];
        __half2 h0 = __floats2half2_rn(v.x, v.y);
        __half2 h1 = __floats2half2_rn(v.z, v.w);
        *(uint2*)&W1KN[k * PADH + n] = make_uint2(*(unsigned*)&h0, *(unsigned*)&h1);
    }

    int m0 = (w & 3) * 16;
    int nbase = (w >> 2) * 32;
    int c4 = lane * 4;

    int sec = lane >> 3, r8 = lane & 7;
    unsigned t_base  = (unsigned)__cvta_generic_to_shared(t_h);
    unsigned w1_base = (unsigned)__cvta_generic_to_shared(W1KN);
    unsigned aAddr = t_base +
        (((m0 + r8 + ((sec & 1) << 3)) * PADH + ((sec >> 1) << 3)) << 1);
    unsigned bAddrT = w1_base +
        (((((sec & 1) << 3) + r8) * PADH + ((sec >> 1) << 3) + nbase) << 1);

    int nTiles = N_EDGES / ET;
    for (int t = blockIdx.x; t < nTiles; t += gridDim.x) {
        int e0 = t * ET;
        __syncthreads();

        if (tid < ET) src_s[tid] = ei[e0 + tid];
        else if (tid < 2 * ET) dst_s[tid - ET] = ei[N_EDGES + e0 + (tid - ET)];
        if (tid < ET * 3) dirn_s[tid] = g_dirn[e0 * 3 + tid];
        __syncthreads();

        // filt = rbf @ Wrbf
        {
            float acc[4][4];
#pragma unroll
            for (int it = 0; it < 4; ++it)
#pragma unroll
                for (int q = 0; q < 4; ++q) acc[it][q] = 0.0f;
#pragma unroll
            for (int ks = 0; ks < 2; ++ks) {
                int k0 = ks * 16;
                unsigned a0 = H2U(&g_rbf[(e0 + m0 + gid) * 32 + k0 + 2 * tig]);
                unsigned a1 = H2U(&g_rbf[(e0 + m0 + gid + 8) * 32 + k0 + 2 * tig]);
                unsigned a2 = H2U(&g_rbf[(e0 + m0 + gid) * 32 + k0 + 2 * tig + 8]);
                unsigned a3 = H2U(&g_rbf[(e0 + m0 + gid + 8) * 32 + k0 + 2 * tig + 8]);
#pragma unroll
                for (int it = 0; it < 4; ++it) {
                    int n0 = nbase + it * 8;
                    unsigned b0 = wrbfp[(n0 + gid) * 16 + 8 * ks + tig];
                    unsigned b1 = wrbfp[(n0 + gid) * 16 + 8 * ks + tig + 4];
                    mma_f16(acc[it], a0, a1, a2, a3, b0, b1);
                }
            }
#pragma unroll
            for (int it = 0; it < 4; ++it) {
                int n0 = nbase + it * 8;
                *(__half2*)&filt_h[(m0 + gid) * PADH + n0 + 2 * tig] =
                    __floats2half2_rn(acc[it][0], acc[it][1]);
                *(__half2*)&filt_h[(m0 + gid + 8) * PADH + n0 + 2 * tig] =
                    __floats2half2_rn(acc[it][2], acc[it][3]);
            }
        }
        __syncthreads();

        // t[e][c] = x[src[e]][c] * filt[e][c]
#pragma unroll
        for (int q = 0; q < 4; ++q) {
            int e = w + 16 * q;
            int s = src_s[e];
            float4 xv = *(const float4*)&g_x[s * 128 + c4];
            uint2 fu = *(const uint2*)&filt_h[e * PADH + c4];
            float2 f01 = __half22float2(*(__half2*)&fu.x);
            float2 f23 = __half22float2(*(__half2*)&fu.y);
            __half2 h0 = __floats2half2_rn(xv.x * f01.x, xv.y * f01.y);
            __half2 h1 = __floats2half2_rn(xv.z * f23.x, xv.w * f23.y);
            *(uint2*)&t_h[e * PADH + c4] = make_uint2(*(unsigned*)&h0, *(unsigned*)&h1);
        }
        __syncthreads();

        // phi = t @ W1
        float acc[4][4];
#pragma unroll
        for (int it = 0; it < 4; ++it)
#pragma unroll
            for (int q = 0; q < 4; ++q) acc[it][q] = 0.0f;
#pragma unroll
        for (int ks = 0; ks < 8; ++ks) {
            unsigned koff_a = ks * 32;
            unsigned koff_b = ks * 16 * PADH * 2;
            unsigned a0, a1, a2, a3;
            ldsm_x4(a0, a1, a2, a3, aAddr + koff_a);
            unsigned b00, b01, b10, b11;
            ldsm_x4_t(b00, b01, b10, b11, bAddrT + koff_b);
            unsigned b20, b21, b30, b31;
            ldsm_x4_t(b20, b21, b30, b31, bAddrT + koff_b + 32);
            mma_f16(acc[0], a0, a1, a2, a3, b00, b01);
            mma_f16(acc[1], a0, a1, a2, a3, b10, b11);
            mma_f16(acc[2], a0, a1, a2, a3, b20, b21);
            mma_f16(acc[3], a0, a1, a2, a3, b30, b31);
        }
        __syncthreads();

#pragma unroll
        for (int it = 0; it < 4; ++it) {
            int n0 = nbase + it * 8;
            *(__half2*)&t_h[(m0 + gid) * PADH + n0 + 2 * tig] =
                __floats2half2_rn(silu(acc[it][0]), silu(acc[it][1]));
            *(__half2*)&t_h[(m0 + gid + 8) * PADH + n0 + 2 * tig] =
                __floats2half2_rn(silu(acc[it][2]), silu(acc[it][3]));
        }
        __syncthreads();

        // scatter
#pragma unroll
        for (int q = 0; q < 4; ++q) {
            int e = w + 16 * q;
            int s = src_s[e], d = dst_s[e];
            uint2 pu = *(const uint2*)&t_h[e * PADH + c4];
            float2 p01 = __half22float2(*(__half2*)&pu.x);
            float2 p23 = __half22float2(*(__half2*)&pu.y);
            float d0 = dirn_s[e * 3 + 0];
            float d1 = dirn_s[e * 3 + 1];
            float d2 = dirn_s[e * 3 + 2];
            red4(&g_dx[d * 128 + c4], p01.x, p01.y, p23.x, p23.y);
            if (novmix) {
                red4(&g_vec[(d * 3 + 0) * 128 + c4],
                     p01.x * d0, p01.y * d0, p23.x * d0, p23.y * d0);
                red4(&g_vec[(d * 3 + 1) * 128 + c4],
                     p01.x * d1, p01.y * d1, p23.x * d1, p23.y * d1);
                red4(&g_vec[(d * 3 + 2) * 128 + c4],
                     p01.x * d2, p01.y * d2, p23.x * d2, p23.y * d2);
            } else {
                uint2 fu = *(const uint2*)&filt_h[e * PADH + c4];
                float2 f01 = __half22float2(*(__half2*)&fu.x);
                float2 f23 = __half22float2(*(__half2*)&fu.y);
                float4 m0v = *(const float4*)&g_vmix[(s * 3 + 0) * 128 + c4];
                red4(&g_vec[(d * 3 + 0) * 128 + c4],
                     m0v.x * f01.x + p01.x * d0, m0v.y * f01.y + p01.y * d0,
                     m0v.z * f23.x + p23.x * d0, m0v.w * f23.y + p23.y * d0);
                float4 m1v = *(const float4*)&g_vmix[(s * 3 + 1) * 128 + c4];
                red4(&g_vec[(d * 3 + 1) * 128 + c4],
                     m1v.x * f01.x + p01.x * d1, m1v.y * f01.y + p01.y * d1,
                     m1v.z * f23.x + p23.x * d1, m1v.w * f23.y + p23.y * d1);
                float4 m2v = *(const float4*)&g_vmix[(s * 3 + 2) * 128 + c4];
                red4(&g_vec[(d * 3 + 2) * 128 + c4],
                     m2v.x * f01.x + p01.x * d2, m2v.y * f01.y + p01.y * d2,
                     m2v.z * f23.x + p23.x * d2, m2v.w * f23.y + p23.y * d2);
            }
        }
    }
}

__global__ void k_pool(const float* __restrict__ a, const int* __restrict__ batch,
                       const float* __restrict__ Wb, const float* __restrict__ bb) {
    __shared__ float Wb_s[128 * 65];
    __shared__ float bb_s[65];
    __shared__ float a_s[4][128];
    int tx = threadIdx.x, ty = threadIdx.y;
    int tid = ty * 65 + tx;
    for (int m = tid; m < 128 * 65; m += 260) Wb_s[m] = Wb[m];
    if (tid < 65) bb_s[tid] = bb[tid];
    __syncthreads();
    for (int base = blockIdx.x * 4; base < N_NODES; base += gridDim.x * 4) {
        int n = base + ty;
        a_s[ty][tx] = a[n * 128 + tx];
        if (tx + 65 < 128) a_s[ty][tx + 65] = a[n * 128 + tx + 65];
        __syncthreads();
        float acc = bb_s[tx];
#pragma unroll 4
        for (int jj = 0; jj < 128; ++jj) acc += a_s[ty][jj] * Wb_s[jj * 65 + tx];
        atomicAdd(&g_pooled[batch[n] * 65 + tx], acc);
        __syncthreads();
    }
}

__global__ void k_final(float* __restrict__ out) {
    int idx = blockIdx.x * blockDim.x + threadIdx.x;
    if (idx < N_GRAPHS * LATENT) {
        int g = idx / LATENT, k = idx % LATENT;
        out[idx] = g_pooled[g * 65 + k];
    } else if (idx < N_GRAPHS * LATENT + N_GRAPHS) {
        int g = idx - N_GRAPHS * LATENT;
        float lv = g_pooled[g * 65 + 64];
        out[idx] = fminf(fmaxf(lv, -10.0f), 2.0f);
    }
}

extern "C" void kernel_launch(void* const* d_in, const int* in_sizes, int n_in,
                              void* d_out, int out_size) {
    (void)in_sizes; (void)n_in; (void)out_size;
    const int* z = (const int*)d_in[0];
    const float* pos = (const float*)d_in[1];
    const int* batch = (const int*)d_in[2];
    const int* ei = (const int*)d_in[3];
    const float* embed = (const float*)d_in[4];
    const float* W_rbf = (const float*)d_in[5];
    const float* W1 = (const float*)d_in[6];
    const float* Wo = (const float*)d_in[7];
    const float* Wv = (const float*)d_in[8];
    const float* Wvec2 = (const float*)d_in[10];
    const float* W_a = (const float*)d_in[11];
    const float* b_a = (const float*)d_in[12];
    const float* W_b = (const float*)d_in[13];
    const float* b_b = (const float*)d_in[14];
    float* out = (float*)d_out;

    float *p_x, *p_vec, *p_vmix, *p_dx, *p_a;
    unsigned* p_wrbfp;
    cudaGetSymbolAddress((void**)&p_x, g_x);
    cudaGetSymbolAddress((void**)&p_vec, g_vec);
    cudaGetSymbolAddress((void**)&p_vmix, g_vmix);
    cudaGetSymbolAddress((void**)&p_dx, g_dx);
    cudaGetSymbolAddress((void**)&p_a, g_a);
    cudaGetSymbolAddress((void**)&p_wrbfp, g_wrbfp);

    size_t smem_g128 = (size_t)(128 * PADH + 64 * 136) * 2;       // 52224
    size_t smem_g256 = (size_t)(256 * PADH + 64 * 264) * 2;       // 103424
    size_t smem_edge = (size_t)(128 * PADH + 2 * ET * PADH) * 2
                       + 192 * 4 + 2 * ET * 4;                    // ~69.3 KB
    cudaFuncSetAttribute(k_gemm2, cudaFuncAttributeMaxDynamicSharedMemorySize, (int)smem_g128);
    cudaFuncSetAttribute(k_gemma, cudaFuncAttributeMaxDynamicSharedMemorySize, (int)smem_g256);
    cudaFuncSetAttribute(k_edge, cudaFuncAttributeMaxDynamicSharedMemorySize, (int)smem_edge);

    int nT_small = (N_NODES + 63) / 64;          // 157
    int nT_big = (N_NODES * 3 + 63) / 64;        // 469

    k_setup<<<(N_NODES * 384 + 255) / 256, 256>>>(z, embed, W_rbf);
    k_geom<<<(N_EDGES + 255) / 256, 256>>>(pos, ei);

    // ---- layer 0 (vmix == 0) ----
    k_edge<<<444, 512, smem_edge>>>(ei, p_wrbfp, W1, 1);
    // merged: x += dx@Wo0 (clear dx) ∥ vmix = vec@Wv1
    k_gemm2<<<nT_small + nT_big, 256, smem_g128>>>(
        p_dx, Wo, p_x, N_NODES, 1,
        p_vec, Wv + 128 * 128, p_vmix, N_NODES * 3);

    // ---- layer 1 ----
    k_edge<<<444, 512, smem_edge>>>(ei, p_wrbfp + 128 * 16, W1 + 128 * 128, 0);
    // merged: x += dx@Wo1 ∥ v2 = vec@Wvec2
    k_gemm2<<<nT_small + nT_big, 256, smem_g128>>>(
        p_dx, Wo + 128 * 128, p_x, N_NODES, 0,
        p_vec, Wvec2, p_vmix, N_NODES * 3);

    // a = silu([x | vnorm(v2)] @ W_a + b_a)
    k_gemma<<<nT_small, 256, smem_g256>>>(p_x, p_vmix, W_a, b_a, p_a, N_NODES);

    dim3 pb(65, 4);
    k_pool<<<296, pb>>>(p_a, batch, W_b, b_b);

    k_final<<<(N_GRAPHS * LATENT + N_GRAPHS + 255) / 256, 256>>>(out);
}

// round 16
// speedup vs baseline: 1.1023x; 1.0466x over previous
#include <cuda_runtime.h>
#include <cuda_fp16.h>
#include <math.h>

#define N_NODES 10000
#define N_EDGES 160000
#define HIDDEN 128
#define NUM_RBF 32
#define N_GRAPHS 128
#define LATENT 64
#define ET 64
#define PADH 136   // half stride for 128-wide rows (272B: conflict-free for LDSM/trans)

// packed fp16 weights [k][n] (filled once by k_setup)
#define WO0_OFF 0
#define WO1_OFF 16384
#define WV1_OFF 32768
#define WVEC2_OFF 49152
#define WA_OFF 65536            // 32768 elems
#define W1_0_OFF 98304
#define W1_1_OFF 114688
#define WH_TOTAL 131072

// ---------------- scratch ----------------
__device__ float g_x[N_NODES * HIDDEN];
__device__ float g_vec[N_NODES * 3 * HIDDEN];
__device__ float g_vmix[N_NODES * 3 * HIDDEN];
__device__ float g_dx[N_NODES * HIDDEN];
__device__ float g_a[N_NODES * HIDDEN];
__device__ float g_dirn[N_EDGES * 3];
__device__ __half g_rbf[N_EDGES * NUM_RBF];
__device__ unsigned g_wrbfp[2 * 128 * 16];
__device__ __half g_wh[WH_TOTAL];
__device__ float g_pooled[N_GRAPHS * 65];

// ---------------- helpers ----------------
__device__ __forceinline__ void mma_f16(float c[4], unsigned a0, unsigned a1,
                                        unsigned a2, unsigned a3,
                                        unsigned b0, unsigned b1) {
    asm volatile(
        "mma.sync.aligned.m16n8k16.row.col.f32.f16.f16.f32 "
        "{%0,%1,%2,%3}, {%4,%5,%6,%7}, {%8,%9}, {%0,%1,%2,%3};"
        : "+f"(c[0]), "+f"(c[1]), "+f"(c[2]), "+f"(c[3])
        : "r"(a0), "r"(a1), "r"(a2), "r"(a3), "r"(b0), "r"(b1));
}

__device__ __forceinline__ void ldsm_x4(unsigned& r0, unsigned& r1,
                                        unsigned& r2, unsigned& r3, unsigned addr) {
    asm volatile("ldmatrix.sync.aligned.m8n8.x4.shared.b16 {%0,%1,%2,%3}, [%4];"
                 : "=r"(r0), "=r"(r1), "=r"(r2), "=r"(r3) : "r"(addr));
}

__device__ __forceinline__ void ldsm_x4_t(unsigned& r0, unsigned& r1,
                                          unsigned& r2, unsigned& r3, unsigned addr) {
    asm volatile("ldmatrix.sync.aligned.m8n8.x4.trans.shared.b16 {%0,%1,%2,%3}, [%4];"
                 : "=r"(r0), "=r"(r1), "=r"(r2), "=r"(r3) : "r"(addr));
}

__device__ __forceinline__ void red4(float* p, float a, float b, float c, float d) {
    unsigned long long addr = (unsigned long long)p;
    asm volatile("red.global.add.v4.f32 [%0], {%1,%2,%3,%4};"
                 :: "l"(addr), "f"(a), "f"(b), "f"(c), "f"(d) : "memory");
}

__device__ __forceinline__ void red2(float* p, float a, float b) {
    unsigned long long addr = (unsigned long long)p;
    asm volatile("red.global.add.v2.f32 [%0], {%1,%2};"
                 :: "l"(addr), "f"(a), "f"(b) : "memory");
}

__device__ __forceinline__ void cp16(unsigned saddr, const void* g) {
    asm volatile("cp.async.ca.shared.global [%0], [%1], 16;"
                 :: "r"(saddr), "l"(g) : "memory");
}
#define CP_COMMIT() asm volatile("cp.async.commit_group;" ::: "memory")
#define CP_WAIT() asm volatile("cp.async.wait_group 0;" ::: "memory")

__device__ __forceinline__ float silu(float v) {
    return __fdividef(v, 1.0f + __expf(-v));
}

#define H2U(p) (*(const unsigned*)(p))

// ---------------- setup: zero scratch + embed + weight packing ----------------
__global__ void k_setup(const int* __restrict__ z, const float* __restrict__ emb,
                        const float* __restrict__ W_rbf,
                        const float* __restrict__ Wo, const float* __restrict__ Wv,
                        const float* __restrict__ Wvec2, const float* __restrict__ W_a,
                        const float* __restrict__ W1) {
    int i = blockIdx.x * blockDim.x + threadIdx.x;
    if (i < N_NODES * 384) g_vec[i] = 0.0f;
    if (i < N_NODES * 128) {
        g_dx[i] = 0.0f;
        int n = i >> 7, j = i & 127;
        g_x[i] = emb[z[n] * HIDDEN + j];
    }
    if (i < N_GRAPHS * 65) g_pooled[i] = 0.0f;
    if (i < 2 * 128 * 16) {
        int l = i >> 11, n = (i >> 4) & 127, kk = i & 15;
        const float* base = W_rbf + l * 32 * 128;
        __half lo = __float2half(base[(2 * kk) * 128 + n]);
        __half hi = __float2half(base[(2 * kk + 1) * 128 + n]);
        __half2 h2 = __halves2half2(lo, hi);
        g_wrbfp[i] = *(unsigned*)&h2;
    }
    if (i < WH_TOTAL) {
        float v;
        if (i < WV1_OFF)              v = Wo[i];                      // Wo0|Wo1
        else if (i < WVEC2_OFF)       v = Wv[16384 + (i - WV1_OFF)];  // Wv layer1
        else if (i < WA_OFF)          v = Wvec2[i - WVEC2_OFF];
        else if (i < W1_0_OFF)        v = W_a[i - WA_OFF];
        else                          v = W1[i - W1_0_OFF];           // W1_0|W1_1
        g_wh[i] = __float2half(v);
    }
}

__global__ void k_geom(const float* __restrict__ pos, const int* __restrict__ ei) {
    int e = blockIdx.x * blockDim.x + threadIdx.x;
    if (e >= N_EDGES) return;
    int s = ei[e], d = ei[N_EDGES + e];
    float dx = pos[d * 3 + 0] - pos[s * 3 + 0];
    float dy = pos[d * 3 + 1] - pos[s * 3 + 1];
    float dz = pos[d * 3 + 2] - pos[s * 3 + 2];
    float r = sqrtf(dx * dx + dy * dy + dz * dz + 1e-8f);
    float inv = 1.0f / r;
    g_dirn[e * 3 + 0] = dx * inv;
    g_dirn[e * 3 + 1] = dy * inv;
    g_dirn[e * 3 + 2] = dz * inv;

    uint4* rp = (uint4*)&g_rbf[e * 32];
    uint4 z4 = make_uint4(0, 0, 0, 0);
    rp[0] = z4; rp[1] = z4; rp[2] = z4; rp[3] = z4;

    if (r < 5.0f) {
        const float c0 = 0.006737946999085467f;
        const float step = (1.0f - c0) / 31.0f;
        const float tmp = (2.0f / 32.0f) * (1.0f - c0);
        const float beta = 1.0f / (tmp * tmp);
        float cut = 0.5f * (__cosf(0.6283185307179586f * r) + 1.0f);
        float er = __expf(-r);
        int kc = (int)((er - c0) * (1.0f / step));
        int base = kc - 8;
        base = base < 0 ? 0 : (base > 15 ? 15 : base);
#pragma unroll
        for (int kk = 0; kk < 17; ++kk) {
            int k = base + kk;
            float m = c0 + (float)k * step;
            float dd = er - m;
            g_rbf[e * 32 + k] = __float2half(cut * __expf(-beta * dd * dd));
        }
    }
}

// ---------------- one 64-row GEMM tile: pre-packed half W via cp.async ----------------
// MODE 0: A row-major RxK.  MODE 2 (K=256): A-row = [x | vnorm(A2)].
template <int K, int MODE>
__device__ __forceinline__ void gemm_tile(
    const float* __restrict__ A, const float* __restrict__ A2,
    const __half* __restrict__ Wh, const float* __restrict__ bias,
    float* __restrict__ C, int R, int r0, int accum, int act, int clearA,
    __half* smh) {
    constexpr int PK = K + 8;
    __half* W_h = smh;            // [K][PADH]
    __half* A_h = W_h + K * PADH; // [64][PK]
    int tid = threadIdx.x;
    int w = tid >> 5, lane = tid & 31, gid = lane >> 2, tig = lane & 3;

    // issue async W copy (half, [k][n]) — lands while we stage A below
    unsigned wsm = (unsigned)__cvta_generic_to_shared(W_h);
    for (int m8 = tid; m8 < K * 16; m8 += 256) {
        int k = m8 >> 4, n = (m8 & 15) * 8;
        cp16(wsm + (unsigned)(k * PADH + n) * 2, Wh + k * 128 + n);
    }
    CP_COMMIT();

    // stage A (fp32 load + convert) while W streams in
    for (int m4 = tid; m4 < 64 * (K / 4); m4 += 256) {
        int r = m4 / (K / 4), c = (m4 % (K / 4)) * 4;
        int rr = r0 + r;
        float4 v = make_float4(0.f, 0.f, 0.f, 0.f);
        if (rr < R) {
            if (MODE == 2) {
                if (c < 128) {
                    v = *(const float4*)&A[rr * 128 + c];
                } else {
                    int cc = c - 128;
                    float4 a0 = *(const float4*)&A2[(rr * 3 + 0) * 128 + cc];
                    float4 a1 = *(const float4*)&A2[(rr * 3 + 1) * 128 + cc];
                    float4 a2 = *(const float4*)&A2[(rr * 3 + 2) * 128 + cc];
                    v.x = sqrtf(a0.x * a0.x + a1.x * a1.x + a2.x * a2.x + 1e-8f);
                    v.y = sqrtf(a0.y * a0.y + a1.y * a1.y + a2.y * a2.y + 1e-8f);
                    v.z = sqrtf(a0.z * a0.z + a1.z * a1.z + a2.z * a2.z + 1e-8f);
                    v.w = sqrtf(a0.w * a0.w + a1.w * a1.w + a2.w * a2.w + 1e-8f);
                }
            } else {
                v = *(const float4*)&A[rr * K + c];
                if (clearA)
                    *(float4*)&((float*)A)[rr * K + c] = make_float4(0.f, 0.f, 0.f, 0.f);
            }
        }
        __half2 h0 = __floats2half2_rn(v.x, v.y);
        __half2 h1 = __floats2half2_rn(v.z, v.w);
        *(uint2*)&A_h[r * PK + c] = make_uint2(*(unsigned*)&h0, *(unsigned*)&h1);
    }
    CP_WAIT();
    __syncthreads();

    int m0 = (w & 3) * 16;
    int nbase = (w >> 2) * 64;
    int sec = lane >> 3, r8 = lane & 7;
    unsigned a_base = (unsigned)__cvta_generic_to_shared(A_h);
    unsigned aAddr = a_base +
        (((m0 + r8 + ((sec & 1) << 3)) * PK + ((sec >> 1) << 3)) << 1);
    unsigned bAddrT = wsm +
        (((((sec & 1) << 3) + r8) * PADH + ((sec >> 1) << 3) + nbase) << 1);

    float acc[8][4];
#pragma unroll
    for (int it = 0; it < 8; ++it)
#pragma unroll
        for (int q = 0; q < 4; ++q) acc[it][q] = 0.0f;

#pragma unroll
    for (int ks = 0; ks < K / 16; ++ks) {
        unsigned koff_a = ks * 32;
        unsigned koff_b = ks * 16 * PADH * 2;
        unsigned a0, a1, a2, a3;
        ldsm_x4(a0, a1, a2, a3, aAddr + koff_a);
#pragma unroll
        for (int j = 0; j < 4; ++j) {
            unsigned b0, b1, b2, b3;
            ldsm_x4_t(b0, b1, b2, b3, bAddrT + koff_b + j * 32);
            mma_f16(acc[2 * j], a0, a1, a2, a3, b0, b1);
            mma_f16(acc[2 * j + 1], a0, a1, a2, a3, b2, b3);
        }
    }

#pragma unroll
    for (int it = 0; it < 8; ++it) {
        int n0 = nbase + it * 8;
        int col = n0 + 2 * tig;
        float bb0 = bias ? bias[col] : 0.0f;
        float bb1 = bias ? bias[col + 1] : 0.0f;
#pragma unroll
        for (int h = 0; h < 2; ++h) {
            int row = r0 + m0 + gid + h * 8;
            if (row < R) {
                float v0 = acc[it][2 * h + 0] + bb0;
                float v1 = acc[it][2 * h + 1] + bb1;
                if (act) { v0 = silu(v0); v1 = silu(v1); }
                if (accum) {
                    red2(&C[row * 128 + col], v0, v1);
                } else {
                    C[row * 128 + col] = v0;
                    C[row * 128 + col + 1] = v1;
                }
            }
        }
    }
}

// merged dual GEMM (one tile per CTA)
__global__ __launch_bounds__(256, 3) void k_gemm2(
    const float* A1, const __half* W1h, float* C1, int R1, int clear1,
    const float* A2, const __half* W2h, float* C2, int R2) {
    extern __shared__ __half smh[];
    int nT1 = (R1 + 63) >> 6;
    if ((int)blockIdx.x < nT1)
        gemm_tile<128, 0>(A1, nullptr, W1h, nullptr, C1, R1, blockIdx.x << 6,
                          1, 0, clear1, smh);
    else
        gemm_tile<128, 0>(A2, nullptr, W2h, nullptr, C2, R2,
                          ((int)blockIdx.x - nT1) << 6, 0, 0, 0, smh);
}

// a = silu([x | vnorm(v2)] @ W_a + b_a)
__global__ __launch_bounds__(256, 2) void k_gemma(
    const float* X, const float* V2, const __half* Wh, const float* bias,
    float* C, int R) {
    extern __shared__ __half smh[];
    gemm_tile<256, 2>(X, V2, Wh, bias, C, R, blockIdx.x << 6, 0, 1, 0, smh);
}

// ---------------- fused fp16 edge kernel (pre-packed W1, cp.async staged) ----------------
__global__ __launch_bounds__(512, 3) void k_edge(
    const int* __restrict__ ei, const unsigned* __restrict__ wrbfp,
    const __half* __restrict__ W1h, int novmix) {
    extern __shared__ __half smh[];
    __half* W1KN   = smh;                      // [128 k][PADH n]
    __half* filt_h = W1KN + 128 * PADH;        // [64 e][PADH c]
    __half* t_h    = filt_h + ET * PADH;       // [64 e][PADH k] (phi alias)
    float* dirn_s = (float*)(t_h + ET * PADH);
    int* src_s = (int*)(dirn_s + 192);
    int* dst_s = src_s + ET;

    int tid = threadIdx.x;
    int w = tid >> 5, lane = tid & 31, gid = lane >> 2, tig = lane & 3;

    // async W1 staging (half [k][n])
    unsigned w1sm = (unsigned)__cvta_generic_to_shared(W1KN);
    for (int m8 = tid; m8 < 128 * 16; m8 += 512) {
        int k = m8 >> 4, n = (m8 & 15) * 8;
        cp16(w1sm + (unsigned)(k * PADH + n) * 2, W1h + k * 128 + n);
    }
    CP_COMMIT();
    CP_WAIT();

    int m0 = (w & 3) * 16;
    int nbase = (w >> 2) * 32;
    int c4 = lane * 4;

    int sec = lane >> 3, r8 = lane & 7;
    unsigned t_base  = (unsigned)__cvta_generic_to_shared(t_h);
    unsigned aAddr = t_base +
        (((m0 + r8 + ((sec & 1) << 3)) * PADH + ((sec >> 1) << 3)) << 1);
    unsigned bAddrT = w1sm +
        (((((sec & 1) << 3) + r8) * PADH + ((sec >> 1) << 3) + nbase) << 1);

    int nTiles = N_EDGES / ET;
    for (int t = blockIdx.x; t < nTiles; t += gridDim.x) {
        int e0 = t * ET;
        __syncthreads();

        if (tid < ET) src_s[tid] = ei[e0 + tid];
        else if (tid < 2 * ET) dst_s[tid - ET] = ei[N_EDGES + e0 + (tid - ET)];
        if (tid < ET * 3) dirn_s[tid] = g_dirn[e0 * 3 + tid];
        __syncthreads();

        // filt = rbf @ Wrbf
        {
            float acc[4][4];
#pragma unroll
            for (int it = 0; it < 4; ++it)
#pragma unroll
                for (int q = 0; q < 4; ++q) acc[it][q] = 0.0f;
#pragma unroll
            for (int ks = 0; ks < 2; ++ks) {
                int k0 = ks * 16;
                unsigned a0 = H2U(&g_rbf[(e0 + m0 + gid) * 32 + k0 + 2 * tig]);
                unsigned a1 = H2U(&g_rbf[(e0 + m0 + gid + 8) * 32 + k0 + 2 * tig]);
                unsigned a2 = H2U(&g_rbf[(e0 + m0 + gid) * 32 + k0 + 2 * tig + 8]);
                unsigned a3 = H2U(&g_rbf[(e0 + m0 + gid + 8) * 32 + k0 + 2 * tig + 8]);
#pragma unroll
                for (int it = 0; it < 4; ++it) {
                    int n0 = nbase + it * 8;
                    unsigned b0 = wrbfp[(n0 + gid) * 16 + 8 * ks + tig];
                    unsigned b1 = wrbfp[(n0 + gid) * 16 + 8 * ks + tig + 4];
                    mma_f16(acc[it], a0, a1, a2, a3, b0, b1);
                }
            }
#pragma unroll
            for (int it = 0; it < 4; ++it) {
                int n0 = nbase + it * 8;
                *(__half2*)&filt_h[(m0 + gid) * PADH + n0 + 2 * tig] =
                    __floats2half2_rn(acc[it][0], acc[it][1]);
                *(__half2*)&filt_h[(m0 + gid + 8) * PADH + n0 + 2 * tig] =
                    __floats2half2_rn(acc[it][2], acc[it][3]);
            }
        }
        __syncthreads();

        // t[e][c] = x[src[e]][c] * filt[e][c]
#pragma unroll
        for (int q = 0; q < 4; ++q) {
            int e = w + 16 * q;
            int s = src_s[e];
            float4 xv = *(const float4*)&g_x[s * 128 + c4];
            uint2 fu = *(const uint2*)&filt_h[e * PADH + c4];
            float2 f01 = __half22float2(*(__half2*)&fu.x);
            float2 f23 = __half22float2(*(__half2*)&fu.y);
            __half2 h0 = __floats2half2_rn(xv.x * f01.x, xv.y * f01.y);
            __half2 h1 = __floats2half2_rn(xv.z * f23.x, xv.w * f23.y);
            *(uint2*)&t_h[e * PADH + c4] = make_uint2(*(unsigned*)&h0, *(unsigned*)&h1);
        }
        __syncthreads();

        // phi = t @ W1
        float acc[4][4];
#pragma unroll
        for (int it = 0; it < 4; ++it)
#pragma unroll
            for (int q = 0; q < 4; ++q) acc[it][q] = 0.0f;
#pragma unroll
        for (int ks = 0; ks < 8; ++ks) {
            unsigned koff_a = ks * 32;
            unsigned koff_b = ks * 16 * PADH * 2;
            unsigned a0, a1, a2, a3;
            ldsm_x4(a0, a1, a2, a3, aAddr + koff_a);
            unsigned b00, b01, b10, b11;
            ldsm_x4_t(b00, b01, b10, b11, bAddrT + koff_b);
            unsigned b20, b21, b30, b31;
            ldsm_x4_t(b20, b21, b30, b31, bAddrT + koff_b + 32);
            mma_f16(acc[0], a0, a1, a2, a3, b00, b01);
            mma_f16(acc[1], a0, a1, a2, a3, b10, b11);
            mma_f16(acc[2], a0, a1, a2, a3, b20, b21);
            mma_f16(acc[3], a0, a1, a2, a3, b30, b31);
        }
        __syncthreads();

#pragma unroll
        for (int it = 0; it < 4; ++it) {
            int n0 = nbase + it * 8;
            *(__half2*)&t_h[(m0 + gid) * PADH + n0 + 2 * tig] =
                __floats2half2_rn(silu(acc[it][0]), silu(acc[it][1]));
            *(__half2*)&t_h[(m0 + gid + 8) * PADH + n0 + 2 * tig] =
                __floats2half2_rn(silu(acc[it][2]), silu(acc[it][3]));
        }
        __syncthreads();

        // scatter
#pragma unroll
        for (int q = 0; q < 4; ++q) {
            int e = w + 16 * q;
            int s = src_s[e], d = dst_s[e];
            uint2 pu = *(const uint2*)&t_h[e * PADH + c4];
            float2 p01 = __half22float2(*(__half2*)&pu.x);
            float2 p23 = __half22float2(*(__half2*)&pu.y);
            float d0 = dirn_s[e * 3 + 0];
            float d1 = dirn_s[e * 3 + 1];
            float d2 = dirn_s[e * 3 + 2];
            red4(&g_dx[d * 128 + c4], p01.x, p01.y, p23.x, p23.y);
            if (novmix) {
                red4(&g_vec[(d * 3 + 0) * 128 + c4],
                     p01.x * d0, p01.y * d0, p23.x * d0, p23.y * d0);
                red4(&g_vec[(d * 3 + 1) * 128 + c4],
                     p01.x * d1, p01.y * d1, p23.x * d1, p23.y * d1);
                red4(&g_vec[(d * 3 + 2) * 128 + c4],
                     p01.x * d2, p01.y * d2, p23.x * d2, p23.y * d2);
            } else {
                uint2 fu = *(const uint2*)&filt_h[e * PADH + c4];
                float2 f01 = __half22float2(*(__half2*)&fu.x);
                float2 f23 = __half22float2(*(__half2*)&fu.y);
                float4 m0v = *(const float4*)&g_vmix[(s * 3 + 0) * 128 + c4];
                red4(&g_vec[(d * 3 + 0) * 128 + c4],
                     m0v.x * f01.x + p01.x * d0, m0v.y * f01.y + p01.y * d0,
                     m0v.z * f23.x + p23.x * d0, m0v.w * f23.y + p23.y * d0);
                float4 m1v = *(const float4*)&g_vmix[(s * 3 + 1) * 128 + c4];
                red4(&g_vec[(d * 3 + 1) * 128 + c4],
                     m1v.x * f01.x + p01.x * d1, m1v.y * f01.y + p01.y * d1,
                     m1v.z * f23.x + p23.x * d1, m1v.w * f23.y + p23.y * d1);
                float4 m2v = *(const float4*)&g_vmix[(s * 3 + 2) * 128 + c4];
                red4(&g_vec[(d * 3 + 2) * 128 + c4],
                     m2v.x * f01.x + p01.x * d2, m2v.y * f01.y + p01.y * d2,
                     m2v.z * f23.x + p23.x * d2, m2v.w * f23.y + p23.y * d2);
            }
        }
    }
}

__global__ void k_pool(const float* __restrict__ a, const int* __restrict__ batch,
                       const float* __restrict__ Wb, const float* __restrict__ bb) {
    __shared__ float Wb_s[128 * 65];
    __shared__ float bb_s[65];
    __shared__ float a_s[4][128];
    int tx = threadIdx.x, ty = threadIdx.y;
    int tid = ty * 65 + tx;
    for (int m = tid; m < 128 * 65; m += 260) Wb_s[m] = Wb[m];
    if (tid < 65) bb_s[tid] = bb[tid];
    __syncthreads();
    for (int base = blockIdx.x * 4; base < N_NODES; base += gridDim.x * 4) {
        int n = base + ty;
        a_s[ty][tx] = a[n * 128 + tx];
        if (tx + 65 < 128) a_s[ty][tx + 65] = a[n * 128 + tx + 65];
        __syncthreads();
        float acc = bb_s[tx];
#pragma unroll 4
        for (int jj = 0; jj < 128; ++jj) acc += a_s[ty][jj] * Wb_s[jj * 65 + tx];
        atomicAdd(&g_pooled[batch[n] * 65 + tx], acc);
        __syncthreads();
    }
}

__global__ void k_final(float* __restrict__ out) {
    int idx = blockIdx.x * blockDim.x + threadIdx.x;
    if (idx < N_GRAPHS * LATENT) {
        int g = idx / LATENT, k = idx % LATENT;
        out[idx] = g_pooled[g * 65 + k];
    } else if (idx < N_GRAPHS * LATENT + N_GRAPHS) {
        int g = idx - N_GRAPHS * LATENT;
        float lv = g_pooled[g * 65 + 64];
        out[idx] = fminf(fmaxf(lv, -10.0f), 2.0f);
    }
}

extern "C" void kernel_launch(void* const* d_in, const int* in_sizes, int n_in,
                              void* d_out, int out_size) {
    (void)in_sizes; (void)n_in; (void)out_size;
    const int* z = (const int*)d_in[0];
    const float* pos = (const float*)d_in[1];
    const int* batch = (const int*)d_in[2];
    const int* ei = (const int*)d_in[3];
    const float* embed = (const float*)d_in[4];
    const float* W_rbf = (const float*)d_in[5];
    const float* W1 = (const float*)d_in[6];
    const float* Wo = (const float*)d_in[7];
    const float* Wv = (const float*)d_in[8];
    const float* Wvec2 = (const float*)d_in[10];
    const float* W_a = (const float*)d_in[11];
    const float* b_a = (const float*)d_in[12];
    const float* W_b = (const float*)d_in[13];
    const float* b_b = (const float*)d_in[14];
    float* out = (float*)d_out;

    float *p_x, *p_vec, *p_vmix, *p_dx, *p_a;
    unsigned* p_wrbfp;
    __half* p_wh;
    cudaGetSymbolAddress((void**)&p_x, g_x);
    cudaGetSymbolAddress((void**)&p_vec, g_vec);
    cudaGetSymbolAddress((void**)&p_vmix, g_vmix);
    cudaGetSymbolAddress((void**)&p_dx, g_dx);
    cudaGetSymbolAddress((void**)&p_a, g_a);
    cudaGetSymbolAddress((void**)&p_wrbfp, g_wrbfp);
    cudaGetSymbolAddress((void**)&p_wh, g_wh);

    size_t smem_g128 = (size_t)(128 * PADH + 64 * 136) * 2;
    size_t smem_g256 = (size_t)(256 * PADH + 64 * 264) * 2;
    size_t smem_edge = (size_t)(128 * PADH + 2 * ET * PADH) * 2
                       + 192 * 4 + 2 * ET * 4;
    cudaFuncSetAttribute(k_gemm2, cudaFuncAttributeMaxDynamicSharedMemorySize, (int)smem_g128);
    cudaFuncSetAttribute(k_gemma, cudaFuncAttributeMaxDynamicSharedMemorySize, (int)smem_g256);
    cudaFuncSetAttribute(k_edge, cudaFuncAttributeMaxDynamicSharedMemorySize, (int)smem_edge);

    int nT_small = (N_NODES + 63) / 64;          // 157
    int nT_big = (N_NODES * 3 + 63) / 64;        // 469

    k_setup<<<(N_NODES * 384 + 255) / 256, 256>>>(z, embed, W_rbf, Wo, Wv, Wvec2, W_a, W1);
    k_geom<<<(N_EDGES + 255) / 256, 256>>>(pos, ei);

    // ---- layer 0 (vmix == 0) ----
    k_edge<<<444, 512, smem_edge>>>(ei, p_wrbfp, p_wh + W1_0_OFF, 1);
    k_gemm2<<<nT_small + nT_big, 256, smem_g128>>>(
        p_dx, p_wh + WO0_OFF, p_x, N_NODES, 1,
        p_vec, p_wh + WV1_OFF, p_vmix, N_NODES * 3);

    // ---- layer 1 ----
    k_edge<<<444, 512, smem_edge>>>(ei, p_wrbfp + 128 * 16, p_wh + W1_1_OFF, 0);
    k_gemm2<<<nT_small + nT_big, 256, smem_g128>>>(
        p_dx, p_wh + WO1_OFF, p_x, N_NODES, 0,
        p_vec, p_wh + WVEC2_OFF, p_vmix, N_NODES * 3);

    // a = silu([x | vnorm(v2)] @ W_a + b_a)
    k_gemma<<<nT_small, 256, smem_g256>>>(p_x, p_vmix, p_wh + WA_OFF, b_a, p_a, N_NODES);

    dim3 pb(65, 4);
    k_pool<<<296, pb>>>(p_a, batch, W_b, b_b);

    k_final<<<(N_GRAPHS * LATENT + N_GRAPHS + 255) / 256, 256>>>(out);
}